// round 2
// baseline (speedup 1.0000x reference)
#include <cuda_runtime.h>
#include <math.h>

static constexpr int NB = 128;     // batch
static constexpr int SL = 256;     // seq len
static constexpr int QL = 8;       // query len
static constexpr int ED = 300;     // embed dim
static constexpr int HD = 300;     // hidden dim
static constexpr int GW = 1200;    // 4*HD gate width
static constexpr int MS = NB * SL; // 32768
static constexpr int MQ = NB * QL; // 1024
static constexpr float EPSN = 1e-12f;

// ---------------- static device scratch (no runtime allocation) ----------------
__device__ float d_Gf[MS * GW];        // input-proj gates, seqs forward  (incl. biases)
__device__ float d_Gb[MS * GW];        // seqs backward
__device__ float d_Gqf[MQ * GW];       // queries forward
__device__ float d_Gqb[MQ * GW];       // queries backward
__device__ float d_Hcat[MS * 2 * HD];  // [N, L, 2H] concat(hf, hb)
__device__ float d_HcatQ[MQ * 2 * HD];
__device__ float d_h[2 * 2 * NB * HD]; // [dir][parity][N*H] ping-pong hidden
__device__ float d_c[2 * NB * HD];     // [dir][N*H] cell
__device__ float d_hq[2 * 2 * NB * HD];
__device__ float d_cq[2 * NB * HD];
__device__ float d_hs[MS * HD];        // encoded seq states
__device__ float d_qenc[MQ * HD];      // encoded query states
__device__ float d_tmp[MS * HD];       // tanh(hs@Wa^T+ba); later reused as P = hs@Wf
__device__ float d_tmpq[MQ * HD];
__device__ float d_s[MS];              // attention logits (seqs)
__device__ float d_sq[MQ];             // attention logits (queries)
__device__ float d_qv[NB * HD];        // pooled query vec
__device__ float d_qp[NB * HD];        // qv @ Wf
__device__ float d_qn[NB * HD];        // normalized

// ---------------- init ----------------
__global__ void init_state() {
    int i = blockIdx.x * blockDim.x + threadIdx.x;
    if (i < 2 * 2 * NB * HD) { d_h[i] = 0.f; d_hq[i] = 0.f; }
    if (i < 2 * NB * HD)     { d_c[i] = 0.f; d_cq[i] = 0.f; }
}

// ---------------- gathered input-projection GEMM ----------------
// G[m, j] = sum_e emb[tok[m], e] * W[j, e] + b1[j] + b2[j]    (M x 1200, K=300)
__global__ void proj_gemm(const int* __restrict__ tok, const float* __restrict__ emb,
                          const float* __restrict__ W, const float* __restrict__ b1,
                          const float* __restrict__ b2, float* __restrict__ G, int M) {
    __shared__ __align__(16) float As[8][128];
    __shared__ __align__(16) float Bs[8][128];
    int tid = threadIdx.x;
    int m0 = blockIdx.y * 128, n0 = blockIdx.x * 128;
    int tx = tid % 16, ty = tid / 16;
    int am = tid >> 1, akq = (tid & 1) * 4;
    int arow = m0 + am;
    const float* aptr = emb + (long)((arow < M) ? tok[arow] : 0) * ED;
    int bcol = n0 + am;
    float acc[8][8];
#pragma unroll
    for (int i = 0; i < 8; i++)
#pragma unroll
        for (int j = 0; j < 8; j++) acc[i][j] = 0.f;

    for (int k0 = 0; k0 < ED; k0 += 8) {
#pragma unroll
        for (int j = 0; j < 4; j++) {
            int kk = k0 + akq + j;
            As[akq + j][am] = (arow < M && kk < ED) ? aptr[kk] : 0.f;
            Bs[akq + j][am] = (bcol < GW && kk < ED) ? W[bcol * ED + kk] : 0.f;
        }
        __syncthreads();
#pragma unroll
        for (int k = 0; k < 8; k++) {
            float4 a0 = *(const float4*)&As[k][ty * 8];
            float4 a1 = *(const float4*)&As[k][ty * 8 + 4];
            float4 c0 = *(const float4*)&Bs[k][tx * 8];
            float4 c1 = *(const float4*)&Bs[k][tx * 8 + 4];
            float av8[8] = {a0.x, a0.y, a0.z, a0.w, a1.x, a1.y, a1.z, a1.w};
            float bv8[8] = {c0.x, c0.y, c0.z, c0.w, c1.x, c1.y, c1.z, c1.w};
#pragma unroll
            for (int i = 0; i < 8; i++)
#pragma unroll
                for (int j = 0; j < 8; j++) acc[i][j] += av8[i] * bv8[j];
        }
        __syncthreads();
    }
#pragma unroll
    for (int i = 0; i < 8; i++) {
        int row = m0 + ty * 8 + i;
        if (row < M) {
#pragma unroll
            for (int j = 0; j < 8; j++) {
                int col = n0 + tx * 8 + j;
                if (col < GW) G[(long)row * GW + col] = acc[i][j] + b1[col] + b2[col];
            }
        }
    }
}

// ---------------- generic SGEMM: C = A @ op(B) (+bias) (+tanh) ----------------
// transB=1: B is [N,K], C = A@B^T.  transB=0: B is [K,N], C = A@B.
__global__ void gemm_k(const float* __restrict__ A, const float* __restrict__ B,
                       const float* __restrict__ bias, float* __restrict__ C,
                       int M, int N, int K, int transB, int act) {
    __shared__ __align__(16) float As[8][128];
    __shared__ __align__(16) float Bs[8][128];
    int tid = threadIdx.x;
    int m0 = blockIdx.y * 128, n0 = blockIdx.x * 128;
    int tx = tid % 16, ty = tid / 16;
    int am = tid >> 1, akq = (tid & 1) * 4;
    int arow = m0 + am;
    int bcol = n0 + am;
    float acc[8][8];
#pragma unroll
    for (int i = 0; i < 8; i++)
#pragma unroll
        for (int j = 0; j < 8; j++) acc[i][j] = 0.f;

    for (int k0 = 0; k0 < K; k0 += 8) {
#pragma unroll
        for (int j = 0; j < 4; j++) {
            int kk = k0 + akq + j;
            As[akq + j][am] = (arow < M && kk < K) ? A[(long)arow * K + kk] : 0.f;
        }
        if (transB) {
#pragma unroll
            for (int j = 0; j < 4; j++) {
                int kk = k0 + akq + j;
                Bs[akq + j][am] = (bcol < N && kk < K) ? B[(long)bcol * K + kk] : 0.f;
            }
        } else {
            for (int i = tid; i < 1024; i += 256) {
                int k = i >> 7, j = i & 127;
                Bs[k][j] = (k0 + k < K && n0 + j < N) ? B[(long)(k0 + k) * N + n0 + j] : 0.f;
            }
        }
        __syncthreads();
#pragma unroll
        for (int k = 0; k < 8; k++) {
            float4 a0 = *(const float4*)&As[k][ty * 8];
            float4 a1 = *(const float4*)&As[k][ty * 8 + 4];
            float4 c0 = *(const float4*)&Bs[k][tx * 8];
            float4 c1 = *(const float4*)&Bs[k][tx * 8 + 4];
            float av8[8] = {a0.x, a0.y, a0.z, a0.w, a1.x, a1.y, a1.z, a1.w};
            float bv8[8] = {c0.x, c0.y, c0.z, c0.w, c1.x, c1.y, c1.z, c1.w};
#pragma unroll
            for (int i = 0; i < 8; i++)
#pragma unroll
                for (int j = 0; j < 8; j++) acc[i][j] += av8[i] * bv8[j];
        }
        __syncthreads();
    }
#pragma unroll
    for (int i = 0; i < 8; i++) {
        int row = m0 + ty * 8 + i;
        if (row < M) {
#pragma unroll
            for (int j = 0; j < 8; j++) {
                int col = n0 + tx * 8 + j;
                if (col < N) {
                    float v = acc[i][j] + (bias ? bias[col] : 0.f);
                    if (act) v = tanhf(v);
                    C[(long)row * N + col] = v;
                }
            }
        }
    }
}

// ---------------- fused LSTM recurrence step ----------------
// One launch per timestep. CTA = 16 batch rows x 32 hidden units (all 4 gates).
// gates = G[t] + h_prev @ Whh^T ; then cell update, h written to ping-pong + Hcat.
__device__ __forceinline__ float sigm(float x) { return 1.f / (1.f + expf(-x)); }

__global__ void lstm_step(const float* __restrict__ WhhF, const float* __restrict__ WhhB,
                          int t, int Lcur, int isq) {
    const int tid = threadIdx.x;
    const int ut = blockIdx.x;   // 0..9 -> units u0..u0+31
    const int bt = blockIdx.y;   // 0..7 -> batch rows n0..n0+15
    const int dir = blockIdx.z;  // 0 fwd, 1 bwd
    const int u0 = ut * 32, n0 = bt * 16;

    const float* Whh = dir ? WhhB : WhhF;
    const float* G = isq ? (dir ? d_Gqb : d_Gqf) : (dir ? d_Gb : d_Gf);
    float* hbase = isq ? d_hq : d_h;
    float* cbuf = (isq ? d_cq : d_c) + dir * (NB * HD);
    const float* hprev = hbase + (dir * 2 + (t & 1)) * (NB * HD);
    float* hnew = hbase + (dir * 2 + ((t + 1) & 1)) * (NB * HD);
    float* Hc = isq ? d_HcatQ : d_Hcat;
    const int tpos = dir ? (Lcur - 1 - t) : t;

    __shared__ float h_s[16 * 304];        // [b][k], zero-padded k 300..303
    __shared__ float W_s[8][128];          // [k][gatecol]
    __shared__ float gs[16 * 128];         // gates per (b, gatecol)

    for (int i = tid; i < 16 * 304; i += 256) {
        int b = i / 304, k = i - b * 304;
        h_s[i] = (k < HD) ? hprev[(n0 + b) * HD + k] : 0.f;
    }

    const int c0 = tid & 63, bg = tid >> 6;        // compute mapping: cols {c0, c0+64}, rows bg*4..+3
    const int lc = tid & 127, kh = tid >> 7;       // loader mapping
    const int lgate = lc >> 5, lu = u0 + (lc & 31);
    const int lrow = lgate * HD + lu;              // Whh gate row

    float acc[4][2] = {{0.f, 0.f}, {0.f, 0.f}, {0.f, 0.f}, {0.f, 0.f}};

    for (int k0 = 0; k0 < HD; k0 += 8) {
        int kk = k0 + kh * 4;
        float4 v = make_float4(0.f, 0.f, 0.f, 0.f);
        if (lu < HD) {
            if (kk + 3 < HD) {
                v = *(const float4*)&Whh[lrow * HD + kk];
            } else {
                float* pv = (float*)&v;
#pragma unroll
                for (int j = 0; j < 4; j++)
                    if (kk + j < HD) pv[j] = Whh[lrow * HD + kk + j];
            }
        }
        W_s[kh * 4 + 0][lc] = v.x;
        W_s[kh * 4 + 1][lc] = v.y;
        W_s[kh * 4 + 2][lc] = v.z;
        W_s[kh * 4 + 3][lc] = v.w;
        __syncthreads();
#pragma unroll
        for (int k = 0; k < 8; k++) {
            float w0 = W_s[k][c0], w1 = W_s[k][c0 + 64];
#pragma unroll
            for (int r = 0; r < 4; r++) {
                float hv = h_s[(bg * 4 + r) * 304 + k0 + k];
                acc[r][0] += hv * w0;
                acc[r][1] += hv * w1;
            }
        }
        __syncthreads();
    }

    // add input-projection gates and stage to smem for cell update
#pragma unroll
    for (int r = 0; r < 4; r++) {
        int b = bg * 4 + r;
        int n = n0 + b;
        int grow = (n * Lcur + tpos) * GW;
#pragma unroll
        for (int cc = 0; cc < 2; cc++) {
            int cidx = c0 + cc * 64;
            int gate = cidx >> 5, u = u0 + (cidx & 31);
            float v = acc[r][cc];
            if (u < HD) v += G[grow + gate * HD + u];
            gs[b * 128 + cidx] = v;
        }
    }
    __syncthreads();

    for (int p = tid; p < 512; p += 256) {
        int b = p >> 5, ul = p & 31, u = u0 + ul;
        if (u < HD) {
            int n = n0 + b;
            float gi = gs[b * 128 + ul];
            float gf = gs[b * 128 + 32 + ul];
            float gg = gs[b * 128 + 64 + ul];
            float go = gs[b * 128 + 96 + ul];
            float cold = cbuf[n * HD + u];
            float cn = sigm(gf) * cold + sigm(gi) * tanhf(gg);
            float hn = sigm(go) * tanhf(cn);
            cbuf[n * HD + u] = cn;
            hnew[n * HD + u] = hn;
            Hc[(n * Lcur + tpos) * (2 * HD) + dir * HD + u] = hn;
        }
    }
}

// ---------------- attention dot: s[m] = dot(X[m,:], av) ----------------
__global__ void att_dot(const float* __restrict__ X, const float* __restrict__ av,
                        float* __restrict__ out, int M) {
    int w = (blockIdx.x * blockDim.x + threadIdx.x) >> 5;
    int lane = threadIdx.x & 31;
    if (w >= M) return;
    const float* x = X + (long)w * HD;
    float a = 0.f;
    for (int d = lane; d < HD; d += 32) a += x[d] * av[d];
#pragma unroll
    for (int o = 16; o; o >>= 1) a += __shfl_down_sync(0xffffffffu, a, o);
    if (lane == 0) out[w] = a;
}

// ---------------- query softmax pool ----------------
__global__ void qpool_k() {
    int n = blockIdx.x, tid = threadIdx.x;  // 128 threads
    __shared__ float sc[QL];
    if (tid < QL) sc[tid] = d_sq[n * QL + tid];
    __syncthreads();
    float mx = -1e30f;
#pragma unroll
    for (int l = 0; l < QL; l++) mx = fmaxf(mx, sc[l]);
    float e[QL], sum = 0.f;
#pragma unroll
    for (int l = 0; l < QL; l++) { e[l] = expf(sc[l] - mx); sum += e[l]; }
    float inv = 1.f / sum;
    for (int d = tid; d < HD; d += 128) {
        float a = 0.f;
#pragma unroll
        for (int l = 0; l < QL; l++) a += e[l] * d_qenc[(n * QL + l) * HD + d];
        d_qv[n * HD + d] = a * inv;
    }
}

// ---------------- normalize query: qn = qp / max(||qp||, eps) ----------------
__global__ void qnorm_k() {
    int n = blockIdx.x, tid = threadIdx.x;  // 128 threads
    __shared__ float red[128];
    float ss = 0.f;
    for (int d = tid; d < HD; d += 128) { float v = d_qp[n * HD + d]; ss += v * v; }
    red[tid] = ss;
    __syncthreads();
    for (int s = 64; s; s >>= 1) { if (tid < s) red[tid] += red[tid + s]; __syncthreads(); }
    float inv = 1.f / fmaxf(sqrtf(red[0]), EPSN);
    for (int d = tid; d < HD; d += 128) d_qn[n * HD + d] = d_qp[n * HD + d] * inv;
}

// ---------------- final: sliding-window combos + cosines + mix ----------------
__global__ void final_k(const float* __restrict__ sw, const float* __restrict__ P,
                        float* __restrict__ out) {
    int w = (blockIdx.x * blockDim.x + threadIdx.x) >> 5;
    int lane = threadIdx.x & 31;
    if (w >= MS) return;
    int n = w >> 8, l = w & 255;
    int ln = (l + 1 < SL) ? l + 1 : SL - 1;
    int lp = (l > 0) ? l - 1 : 0;
    float sl = d_s[n * SL + l];
    float sn = d_s[n * SL + ln];
    float sp = d_s[n * SL + lp];
    // fwd weights: softmax([sl, sn])
    float m1 = fmaxf(sl, sn);
    float e0 = expf(sl - m1), e1 = expf(sn - m1);
    float wf0 = e0 / (e0 + e1), wf1 = 1.f - wf0;
    // bwd weights: softmax([sp, sl])
    float m2 = fmaxf(sp, sl);
    float f0 = expf(sp - m2), f1 = expf(sl - m2);
    float wb0 = f0 / (f0 + f1), wb1 = 1.f - wb0;

    const float* Pl = P + (long)(n * SL + l) * HD;
    const float* Pn = P + (long)(n * SL + ln) * HD;
    const float* Pp = P + (long)(n * SL + lp) * HD;
    const float* q = d_qn + n * HD;

    float dpq = 0.f, dpp = 0.f, duq = 0.f, duu = 0.f, dvq = 0.f, dvv = 0.f;
    for (int d = lane; d < HD; d += 32) {
        float p = Pl[d], pn = Pn[d], pp = Pp[d], qd = q[d];
        float u = wf0 * p + wf1 * pn;
        float v = wb0 * pp + wb1 * p;
        dpq += p * qd; dpp += p * p;
        duq += u * qd; duu += u * u;
        dvq += v * qd; dvv += v * v;
    }
#pragma unroll
    for (int o = 16; o; o >>= 1) {
        dpq += __shfl_down_sync(0xffffffffu, dpq, o);
        dpp += __shfl_down_sync(0xffffffffu, dpp, o);
        duq += __shfl_down_sync(0xffffffffu, duq, o);
        duu += __shfl_down_sync(0xffffffffu, duu, o);
        dvq += __shfl_down_sync(0xffffffffu, dvq, o);
        dvv += __shfl_down_sync(0xffffffffu, dvv, o);
    }
    if (lane == 0) {
        float c1 = dpq / fmaxf(sqrtf(dpp), EPSN);
        float c2 = duq / fmaxf(sqrtf(duu), EPSN);
        float c3 = dvq / fmaxf(sqrtf(dvv), EPSN);
        out[w] = c1 * sw[0] + c2 * sw[1] + c3 * sw[2];
    }
}

// ---------------- launch ----------------
extern "C" void kernel_launch(void* const* d_in, const int* in_sizes, int n_in,
                              void* d_out, int out_size) {
    const int*   seqs = (const int*)d_in[0];
    const int*   quer = (const int*)d_in[1];
    const float* emb  = (const float*)d_in[2];
    const float* WihF = (const float*)d_in[3];
    const float* WhhF = (const float*)d_in[4];
    const float* bihF = (const float*)d_in[5];
    const float* bhhF = (const float*)d_in[6];
    const float* WihB = (const float*)d_in[7];
    const float* WhhB = (const float*)d_in[8];
    const float* bihB = (const float*)d_in[9];
    const float* bhhB = (const float*)d_in[10];
    const float* Wc   = (const float*)d_in[11];
    const float* bc   = (const float*)d_in[12];
    const float* Wa   = (const float*)d_in[13];
    const float* ba   = (const float*)d_in[14];
    const float* av   = (const float*)d_in[15];
    const float* Wf   = (const float*)d_in[16];
    const float* sw   = (const float*)d_in[17];

    void* p;
    cudaGetSymbolAddress(&p, d_Gf);    float* pGf    = (float*)p;
    cudaGetSymbolAddress(&p, d_Gb);    float* pGb    = (float*)p;
    cudaGetSymbolAddress(&p, d_Gqf);   float* pGqf   = (float*)p;
    cudaGetSymbolAddress(&p, d_Gqb);   float* pGqb   = (float*)p;
    cudaGetSymbolAddress(&p, d_Hcat);  float* pHcat  = (float*)p;
    cudaGetSymbolAddress(&p, d_HcatQ); float* pHcatQ = (float*)p;
    cudaGetSymbolAddress(&p, d_hs);    float* phs    = (float*)p;
    cudaGetSymbolAddress(&p, d_qenc);  float* pqenc  = (float*)p;
    cudaGetSymbolAddress(&p, d_tmp);   float* ptmp   = (float*)p;  // doubles as P
    cudaGetSymbolAddress(&p, d_tmpq);  float* ptmpq  = (float*)p;
    cudaGetSymbolAddress(&p, d_s);     float* ps     = (float*)p;
    cudaGetSymbolAddress(&p, d_sq);    float* psq    = (float*)p;
    cudaGetSymbolAddress(&p, d_qv);    float* pqv    = (float*)p;
    cudaGetSymbolAddress(&p, d_qp);    float* pqp    = (float*)p;

    init_state<<<(2 * 2 * NB * HD + 255) / 256, 256>>>();

    // input projections (gather + GEMM + both biases)
    dim3 gp(10, 256);
    proj_gemm<<<gp, 256>>>(seqs, emb, WihF, bihF, bhhF, pGf, MS);
    proj_gemm<<<gp, 256>>>(seqs, emb, WihB, bihB, bhhB, pGb, MS);
    dim3 gpq(10, 8);
    proj_gemm<<<gpq, 256>>>(quer, emb, WihF, bihF, bhhF, pGqf, MQ);
    proj_gemm<<<gpq, 256>>>(quer, emb, WihB, bihB, bhhB, pGqb, MQ);

    // recurrences (both directions per launch; batch-partitioned, no grid sync)
    dim3 gl(10, 8, 2);
    for (int t = 0; t < SL; t++) lstm_step<<<gl, 256>>>(WhhF, WhhB, t, SL, 0);
    for (int t = 0; t < QL; t++) lstm_step<<<gl, 256>>>(WhhF, WhhB, t, QL, 1);

    // combine directions: hs = Hcat @ Wc^T + bc
    gemm_k<<<dim3(3, 256), 256>>>(pHcat, Wc, bc, phs, MS, HD, 2 * HD, 1, 0);
    gemm_k<<<dim3(3, 8), 256>>>(pHcatQ, Wc, bc, pqenc, MQ, HD, 2 * HD, 1, 0);

    // attention logits: tanh(X @ Wa^T + ba) . att_vec
    gemm_k<<<dim3(3, 256), 256>>>(phs, Wa, ba, ptmp, MS, HD, HD, 1, 1);
    gemm_k<<<dim3(3, 8), 256>>>(pqenc, Wa, ba, ptmpq, MQ, HD, HD, 1, 1);
    att_dot<<<MS / 8, 256>>>(ptmp, av, ps, MS);
    att_dot<<<MQ / 8, 256>>>(ptmpq, av, psq, MQ);

    // pooled, projected, normalized query
    qpool_k<<<NB, 128>>>();
    gemm_k<<<dim3(3, 1), 256>>>(pqv, Wf, nullptr, pqp, NB, HD, HD, 0, 0);
    qnorm_k<<<NB, 128>>>();

    // P = hs @ Wf  (fwd/bwd combos are linear in hs, so one projection suffices)
    // reuses d_tmp (att pre-logits fully consumed by att_dot above)
    gemm_k<<<dim3(3, 256), 256>>>(phs, Wf, nullptr, ptmp, MS, HD, HD, 0, 0);

    final_k<<<MS / 8, 256>>>(sw, ptmp, (float*)d_out);
}